// round 4
// baseline (speedup 1.0000x reference)
#include <cuda_runtime.h>
#include <cstdint>
#include <cmath>

// ---------------- problem constants ----------------
#define Nn 8192
#define Dd 64
#define Pp 32
#define Mm 50
#define Hh 512
#define KX 96              // D + P  (s column folded separately)

// ---------------- tiling ----------------
#define Rr 64              // rows per CTA
#define NBLOCKS (Nn / Rr)  // 128
#define THREADS 512        // 16 warps -> 4 per SMSP (latency hiding)
#define CHUNK 64           // H columns per chunk
#define NCHUNK (Hh / CHUNK)

// padded strides (floats); all ≡ 4 (mod 32) and ≡ 0 (mod 4)
#define XS 100             // sX row stride
#define HS 68              // sH row stride
#define W1S 100            // W1t image: [64 c][100] per chunk
#define W1IMG (CHUNK * W1S)      // 6400 floats
#define W2S 516            // W2t: [64 d][516]
#define W2SZ (Dd * W2S)          // 33024 floats

// smem layout (float offsets)
#define OFF_W2T 0
#define OFF_W1  (OFF_W2T + W2SZ)
#define OFF_X   (OFF_W1 + 2 * W1IMG)
#define OFF_H   (OFF_X + Rr * XS)
#define OFF_B1  (OFF_H + Rr * HS)
#define OFF_W0  (OFF_B1 + Hh)
#define SMEM_FLOATS (OFF_W0 + Hh)
#define SMEM_BYTES (SMEM_FLOATS * 4)      // 230400

typedef unsigned long long u64;

__device__ float gW1t[NCHUNK * W1IMG];    // [chunk][c][k]
__device__ float gW2t[W2SZ];              // [d][k]

// ---------------- helpers ----------------
__device__ __forceinline__ void fma2(u64& acc, u64 a, u64 b) {
    asm("fma.rn.f32x2 %0, %1, %2, %0;" : "+l"(acc) : "l"(a), "l"(b));
}
__device__ __forceinline__ float2 upk(u64 v) {
    float2 r; asm("mov.b64 {%0,%1}, %2;" : "=f"(r.x), "=f"(r.y) : "l"(v)); return r;
}
__device__ __forceinline__ float fast_tanh(float x) {
    float y; asm("tanh.approx.f32 %0, %1;" : "=f"(y) : "f"(x)); return y;
}
__device__ __forceinline__ void cp16(uint32_t dst, const float* src) {
    asm volatile("cp.async.cg.shared.global [%0], [%1], 16;" :: "r"(dst), "l"(src));
}
#define CP_COMMIT() asm volatile("cp.async.commit_group;")
#define CP_WAIT1()  asm volatile("cp.async.wait_group 1;")

// ---------------- setup: transpose weights ----------------
__global__ void transpose_weights(const float* __restrict__ W1,
                                  const float* __restrict__ W2) {
    int tid = blockIdx.x * blockDim.x + threadIdx.x;
    int stride = gridDim.x * blockDim.x;
    for (int i = tid; i < NCHUNK * CHUNK * KX; i += stride) {
        int ch = i / (CHUNK * KX);
        int r  = i % (CHUNK * KX);
        int c  = r / KX;
        int k  = r % KX;
        gW1t[ch * W1IMG + c * W1S + k] = W1[(size_t)(k + 1) * Hh + ch * CHUNK + c];
    }
    for (int i = tid; i < Dd * Hh; i += stride) {
        int d = i / Hh;
        int k = i % Hh;
        gW2t[d * W2S + k] = W2[(size_t)k * Dd + d];
    }
}

// ---------------- main persistent rollout kernel ----------------
__global__ void __launch_bounds__(THREADS, 1) sim_rollout_kernel(
    const float* __restrict__ X0, const float* __restrict__ V0,
    const float* __restrict__ Y,  const float* __restrict__ theta,
    const float* __restrict__ W1, const float* __restrict__ b1,
    const float* __restrict__ W2, const float* __restrict__ b2,
    const float* __restrict__ noise, const int* __restrict__ obs_index,
    float* __restrict__ out)
{
    extern __shared__ float sm[];
    float* sW2t = sm + OFF_W2T;
    float* sW1  = sm + OFF_W1;
    float* sX   = sm + OFF_X;
    float* sH   = sm + OFF_H;
    float* sB1  = sm + OFF_B1;
    float* sW0  = sm + OFF_W0;

    const int tid = threadIdx.x;
    const int w   = tid >> 5;            // 0..15
    const int l   = tid & 31;
    const int row0 = blockIdx.x * Rr;

    // warp owns 4 consecutive rows [w*4, w*4+4); thread: 2 rows, 4 cols stride 16
    const int rg2 = l >> 4;              // 0..1
    const int cq  = l & 15;              // 0..15
    const int r0  = w * 4 + rg2 * 2;     // rows r0, r0+1
    // cols/d: cq + 16*j, j = 0..3

    const float dt   = 1.0f / (float)Mm;
    const float sqdt = sqrtf(dt);
    const int obs = *obs_index;

    // ---- one-time staging ----
    for (int idx = tid; idx < W2SZ / 4; idx += THREADS)
        ((float4*)sW2t)[idx] = ((const float4*)gW2t)[idx];
    for (int idx = tid; idx < Rr * Dd; idx += THREADS) {
        int r = idx >> 6, d = idx & 63;
        sX[r * XS + d] = X0[(size_t)(row0 + r) * Dd + d];
    }
    for (int idx = tid; idx < Rr * Pp; idx += THREADS) {
        int r = idx >> 5, p = idx & 31;
        sX[r * XS + 64 + p] = Y[(size_t)(row0 + r) * Pp + obs * Pp + p];
    }
    for (int idx = tid; idx < Hh; idx += THREADS) {
        sB1[idx] = b1[idx];
        sW0[idx] = W1[idx];              // W1 row 0 (s-column weights)
    }

    // per-thread constants over the 4 d-columns (cq + 16j)
    float thc[4], b2c[4];
    #pragma unroll
    for (int j = 0; j < 4; j++) {
        thc[j] = theta[cq + 16 * j];
        b2c[j] = b2[cq + 16 * j];
    }
    // V state (meaningful at cq == 0)
    float vreg[2];
    #pragma unroll
    for (int i = 0; i < 2; i++) vreg[i] = V0[row0 + r0 + i];

    // prime cp.async: chunk 0 -> buffer 0
    const uint32_t w1sa = (uint32_t)__cvta_generic_to_shared(sW1);
    for (int idx = tid; idx < W1IMG / 4; idx += THREADS)
        cp16(w1sa + idx * 16, gW1t + idx * 4);
    CP_COMMIT();

    const float* aP1 = sX + r0 * XS;
    const float* aP2 = sH + r0 * HS;

    // ---- 50-step rollout ----
    for (int m = 0; m < Mm; ++m) {
        const float s = (float)m * dt;

        // this step's noise
        float nz[2][4];
        const float* nb = noise + ((size_t)m * Nn + row0) * Dd;
        #pragma unroll
        for (int i = 0; i < 2; i++)
            #pragma unroll
            for (int j = 0; j < 4; j++)
                nz[i][j] = nb[(size_t)(r0 + i) * Dd + cq + 16 * j];

        u64 zacc[2][4];
        #pragma unroll
        for (int i = 0; i < 2; i++)
            #pragma unroll
            for (int j = 0; j < 4; j++) zacc[i][j] = 0ull;

        for (int ch = 0; ch < NCHUNK; ++ch) {
            // prefetch next chunk's W1 image into the other buffer
            {
                int nxt = (ch + 1) & 7;
                uint32_t dst = w1sa + (uint32_t)(((ch + 1) & 1) * W1IMG) * 4u;
                const float* src = gW1t + nxt * W1IMG;
                for (int idx = tid; idx < W1IMG / 4; idx += THREADS)
                    cp16(dst + idx * 16, src + idx * 4);
                CP_COMMIT();
            }
            CP_WAIT1();
            __syncthreads();

            const float* w1b = sW1 + (ch & 1) * W1IMG + cq * W1S;

            // per-chunk h-bias: s*W1[0][c] + b1[c]
            float hb[4];
            #pragma unroll
            for (int j = 0; j < 4; j++) {
                int c = ch * CHUNK + cq + 16 * j;
                hb[j] = s * sW0[c] + sB1[c];
            }

            // ---- GEMM1: h(2 rows x 4 cols per thread) ----
            u64 acc[2][4];
            #pragma unroll
            for (int i = 0; i < 2; i++)
                #pragma unroll
                for (int j = 0; j < 4; j++) acc[i][j] = 0ull;

            #pragma unroll 8
            for (int q = 0; q < KX / 4; ++q) {
                ulonglong2 A[2], B[4];
                #pragma unroll
                for (int i = 0; i < 2; i++)          // 2 distinct addrs/warp: broadcast
                    A[i] = *(const ulonglong2*)(aP1 + i * XS + q * 4);
                #pragma unroll
                for (int j = 0; j < 4; j++)          // 16 distinct, stride ≡ 4 mod 32
                    B[j] = *(const ulonglong2*)(w1b + j * 16 * W1S + q * 4);
                #pragma unroll
                for (int i = 0; i < 2; i++)
                    #pragma unroll
                    for (int j = 0; j < 4; j++) {
                        fma2(acc[i][j], A[i].x, B[j].x);
                        fma2(acc[i][j], A[i].y, B[j].y);
                    }
            }

            // bias + tanh -> sH (warp-local rows)
            #pragma unroll
            for (int i = 0; i < 2; i++)
                #pragma unroll
                for (int j = 0; j < 4; j++) {
                    float2 t = upk(acc[i][j]);
                    sH[(r0 + i) * HS + cq + 16 * j] = fast_tanh(t.x + t.y + hb[j]);
                }
            __syncwarp();

            // ---- GEMM2: Z += h @ W2chunk ----
            const float* w2b = sW2t + cq * W2S + ch * CHUNK;
            #pragma unroll 8
            for (int q = 0; q < CHUNK / 4; ++q) {
                ulonglong2 A[2], B[4];
                #pragma unroll
                for (int i = 0; i < 2; i++)
                    A[i] = *(const ulonglong2*)(aP2 + i * HS + q * 4);
                #pragma unroll
                for (int j = 0; j < 4; j++)
                    B[j] = *(const ulonglong2*)(w2b + j * 16 * W2S + q * 4);
                #pragma unroll
                for (int i = 0; i < 2; i++)
                    #pragma unroll
                    for (int j = 0; j < 4; j++) {
                        fma2(zacc[i][j], A[i].x, B[j].x);
                        fma2(zacc[i][j], A[i].y, B[j].y);
                    }
            }
        }

        // ---- epilogue: V and X updates (warp-local) ----
        #pragma unroll
        for (int i = 0; i < 2; i++) {
            float vpart = 0.0f;
            #pragma unroll
            for (int j = 0; j < 4; j++) {
                float2 t = upk(zacc[i][j]);
                float z  = t.x + t.y + b2c[j];
                float wm = sqdt * nz[i][j];
                vpart += z * wm - 0.5f * dt * z * z;
                float* xp = &sX[(r0 + i) * XS + cq + 16 * j];
                float xo = *xp;
                *xp = xo + dt * (thc[j] - xo - z) + wm;
            }
            vpart += __shfl_down_sync(0xffffffffu, vpart, 8, 16);
            vpart += __shfl_down_sync(0xffffffffu, vpart, 4, 16);
            vpart += __shfl_down_sync(0xffffffffu, vpart, 2, 16);
            vpart += __shfl_down_sync(0xffffffffu, vpart, 1, 16);
            vreg[i] += vpart;
        }
        __syncwarp();
    }

    __syncthreads();
    // ---- output: X then V ----
    for (int idx = tid; idx < Rr * Dd; idx += THREADS) {
        int r = idx >> 6, d = idx & 63;
        out[(size_t)(row0 + r) * Dd + d] = sX[r * XS + d];
    }
    if (cq == 0) {
        #pragma unroll
        for (int i = 0; i < 2; i++)
            out[(size_t)Nn * Dd + row0 + r0 + i] = vreg[i];
    }
}

extern "C" void kernel_launch(void* const* d_in, const int* in_sizes, int n_in,
                              void* d_out, int out_size)
{
    (void)in_sizes; (void)n_in; (void)out_size;
    cudaFuncSetAttribute(sim_rollout_kernel,
                         cudaFuncAttributeMaxDynamicSharedMemorySize, SMEM_BYTES);

    transpose_weights<<<64, 256>>>((const float*)d_in[4], (const float*)d_in[6]);
    sim_rollout_kernel<<<NBLOCKS, THREADS, SMEM_BYTES>>>(
        (const float*)d_in[0], (const float*)d_in[1], (const float*)d_in[2],
        (const float*)d_in[3], (const float*)d_in[4], (const float*)d_in[5],
        (const float*)d_in[6], (const float*)d_in[7], (const float*)d_in[8],
        (const int*)d_in[9],   (float*)d_out);
}

// round 5
// speedup vs baseline: 1.6156x; 1.6156x over previous
#include <cuda_runtime.h>
#include <cstdint>
#include <cmath>

// ---------------- problem constants ----------------
#define Nn 8192
#define Dd 64
#define Pp 32
#define Mm 50
#define Hh 512
#define KX 96              // D + P  (s column folded separately)

// ---------------- tiling ----------------
#define Rr 64              // rows per CTA
#define NBLOCKS (Nn / Rr)  // 128
#define THREADS 256        // 8 warps: B-traffic sweet spot (see R4 post-mortem)
#define CHUNK 64           // H columns per chunk
#define NCHUNK (Hh / CHUNK)
#define KQ1 (KX / 4)       // 24 k-quads in GEMM1
#define KQ2 (CHUNK / 4)    // 16 k-quads in GEMM2

// padded strides (floats); all ≡ 4 (mod 32) and ≡ 0 (mod 4)
#define XS 100             // sX row stride
#define HS 68              // sH row stride
#define W1S 100            // W1t image: [64 c][100] per chunk
#define W1IMG (CHUNK * W1S)      // 6400 floats
#define W2S 516            // W2t: [64 d][516]
#define W2SZ (Dd * W2S)          // 33024 floats

// smem layout (float offsets)
#define OFF_W2T 0
#define OFF_W1  (OFF_W2T + W2SZ)
#define OFF_X   (OFF_W1 + 2 * W1IMG)
#define OFF_H   (OFF_X + Rr * XS)
#define OFF_B1  (OFF_H + Rr * HS)
#define OFF_W0  (OFF_B1 + Hh)
#define SMEM_FLOATS (OFF_W0 + Hh)
#define SMEM_BYTES (SMEM_FLOATS * 4)      // 230400

typedef unsigned long long u64;

__device__ float gW1t[NCHUNK * W1IMG];    // [chunk][c][k]
__device__ float gW2t[W2SZ];              // [d][k]

// ---------------- helpers ----------------
__device__ __forceinline__ void fma2(u64& acc, u64 a, u64 b) {
    asm("fma.rn.f32x2 %0, %1, %2, %0;" : "+l"(acc) : "l"(a), "l"(b));
}
__device__ __forceinline__ float2 upk(u64 v) {
    float2 r; asm("mov.b64 {%0,%1}, %2;" : "=f"(r.x), "=f"(r.y) : "l"(v)); return r;
}
__device__ __forceinline__ float fast_tanh(float x) {
    float y; asm("tanh.approx.f32 %0, %1;" : "=f"(y) : "f"(x)); return y;
}
__device__ __forceinline__ void cp16(uint32_t dst, const float* src) {
    asm volatile("cp.async.cg.shared.global [%0], [%1], 16;" :: "r"(dst), "l"(src));
}
#define CP_COMMIT() asm volatile("cp.async.commit_group;")
#define CP_WAIT1()  asm volatile("cp.async.wait_group 1;")

// ---------------- setup: transpose weights ----------------
__global__ void transpose_weights(const float* __restrict__ W1,
                                  const float* __restrict__ W2) {
    int tid = blockIdx.x * blockDim.x + threadIdx.x;
    int stride = gridDim.x * blockDim.x;
    for (int i = tid; i < NCHUNK * CHUNK * KX; i += stride) {
        int ch = i / (CHUNK * KX);
        int r  = i % (CHUNK * KX);
        int c  = r / KX;
        int k  = r % KX;
        gW1t[ch * W1IMG + c * W1S + k] = W1[(size_t)(k + 1) * Hh + ch * CHUNK + c];
    }
    for (int i = tid; i < Dd * Hh; i += stride) {
        int d = i / Hh;
        int k = i % Hh;
        gW2t[d * W2S + k] = W2[(size_t)k * Dd + d];
    }
}

// ---------------- main persistent rollout kernel ----------------
__global__ void __launch_bounds__(THREADS, 1) sim_rollout_kernel(
    const float* __restrict__ X0, const float* __restrict__ V0,
    const float* __restrict__ Y,  const float* __restrict__ theta,
    const float* __restrict__ W1, const float* __restrict__ b1,
    const float* __restrict__ W2, const float* __restrict__ b2,
    const float* __restrict__ noise, const int* __restrict__ obs_index,
    float* __restrict__ out)
{
    extern __shared__ float sm[];
    float* sW2t = sm + OFF_W2T;
    float* sW1  = sm + OFF_W1;
    float* sX   = sm + OFF_X;
    float* sH   = sm + OFF_H;
    float* sB1  = sm + OFF_B1;
    float* sW0  = sm + OFF_W0;

    const int tid = threadIdx.x;
    const int w   = tid >> 5;
    const int l   = tid & 31;
    const int row0 = blockIdx.x * Rr;

    // warp owns 8 consecutive rows; thread: 4 consecutive rows, 4 cols stride 16
    const int rg2 = l >> 4;              // 0..1
    const int cq  = l & 15;              // 0..15
    const int r0  = w * 8 + rg2 * 4;     // rows r0..r0+3

    const float dt   = 1.0f / (float)Mm;
    const float sqdt = sqrtf(dt);
    const int obs = *obs_index;

    // ---- one-time staging ----
    for (int idx = tid; idx < W2SZ / 4; idx += THREADS)
        ((float4*)sW2t)[idx] = ((const float4*)gW2t)[idx];
    for (int idx = tid; idx < Rr * Dd; idx += THREADS) {
        int r = idx >> 6, d = idx & 63;
        sX[r * XS + d] = X0[(size_t)(row0 + r) * Dd + d];
    }
    for (int idx = tid; idx < Rr * Pp; idx += THREADS) {
        int r = idx >> 5, p = idx & 31;
        sX[r * XS + 64 + p] = Y[(size_t)(row0 + r) * Pp + obs * Pp + p];
    }
    for (int idx = tid; idx < Hh; idx += THREADS) {
        sB1[idx] = b1[idx];
        sW0[idx] = W1[idx];              // W1 row 0 (s-column weights)
    }

    float thc[4], b2c[4];
    #pragma unroll
    for (int j = 0; j < 4; j++) {
        thc[j] = theta[cq + 16 * j];
        b2c[j] = b2[cq + 16 * j];
    }
    float vreg[4];
    #pragma unroll
    for (int i = 0; i < 4; i++) vreg[i] = V0[row0 + r0 + i];

    // prime cp.async: chunk 0 -> buffer 0
    const uint32_t w1sa = (uint32_t)__cvta_generic_to_shared(sW1);
    for (int idx = tid; idx < W1IMG / 4; idx += THREADS)
        cp16(w1sa + idx * 16, gW1t + idx * 4);
    CP_COMMIT();

    const float* aP1 = sX + r0 * XS;
    const float* aP2 = sH + r0 * HS;

    // ---- 50-step rollout ----
    for (int m = 0; m < Mm; ++m) {
        const float s = (float)m * dt;

        float nz[4][4];
        const float* nb = noise + ((size_t)m * Nn + row0) * Dd;
        #pragma unroll
        for (int i = 0; i < 4; i++)
            #pragma unroll
            for (int j = 0; j < 4; j++)
                nz[i][j] = nb[(size_t)(r0 + i) * Dd + cq + 16 * j];

        u64 zacc[4][4];
        #pragma unroll
        for (int i = 0; i < 4; i++)
            #pragma unroll
            for (int j = 0; j < 4; j++) zacc[i][j] = 0ull;

        for (int ch = 0; ch < NCHUNK; ++ch) {
            // prefetch next chunk's W1 image into the other buffer
            {
                int nxt = (ch + 1) & 7;
                uint32_t dst = w1sa + (uint32_t)(((ch + 1) & 1) * W1IMG) * 4u;
                const float* src = gW1t + nxt * W1IMG;
                for (int idx = tid; idx < W1IMG / 4; idx += THREADS)
                    cp16(dst + idx * 16, src + idx * 4);
                CP_COMMIT();
            }
            CP_WAIT1();
            __syncthreads();

            const float* w1b = sW1 + (ch & 1) * W1IMG + cq * W1S;

            float hb[4];
            #pragma unroll
            for (int j = 0; j < 4; j++) {
                int c = ch * CHUNK + cq + 16 * j;
                hb[j] = s * sW0[c] + sB1[c];
            }

            // ---- GEMM1, software-pipelined one quad ahead ----
            u64 acc[4][4];
            #pragma unroll
            for (int i = 0; i < 4; i++)
                #pragma unroll
                for (int j = 0; j < 4; j++) acc[i][j] = 0ull;

            {
                ulonglong2 A[2][4], B[2][4];
                #pragma unroll
                for (int i = 0; i < 4; i++)
                    A[0][i] = *(const ulonglong2*)(aP1 + i * XS);
                #pragma unroll
                for (int j = 0; j < 4; j++)
                    B[0][j] = *(const ulonglong2*)(w1b + j * 16 * W1S);

                #pragma unroll
                for (int q = 0; q < KQ1; ++q) {
                    const int cur = q & 1, nxt = cur ^ 1;
                    if (q + 1 < KQ1) {
                        #pragma unroll
                        for (int i = 0; i < 4; i++)
                            A[nxt][i] = *(const ulonglong2*)(aP1 + i * XS + (q + 1) * 4);
                        #pragma unroll
                        for (int j = 0; j < 4; j++)
                            B[nxt][j] = *(const ulonglong2*)(w1b + j * 16 * W1S + (q + 1) * 4);
                    }
                    #pragma unroll
                    for (int i = 0; i < 4; i++)
                        #pragma unroll
                        for (int j = 0; j < 4; j++) {
                            fma2(acc[i][j], A[cur][i].x, B[cur][j].x);
                            fma2(acc[i][j], A[cur][i].y, B[cur][j].y);
                        }
                }
            }

            // bias + tanh -> sH (warp-local rows)
            #pragma unroll
            for (int i = 0; i < 4; i++)
                #pragma unroll
                for (int j = 0; j < 4; j++) {
                    float2 t = upk(acc[i][j]);
                    sH[(r0 + i) * HS + cq + 16 * j] = fast_tanh(t.x + t.y + hb[j]);
                }
            __syncwarp();

            // ---- GEMM2, software-pipelined one quad ahead ----
            {
                const float* w2b = sW2t + cq * W2S + ch * CHUNK;
                ulonglong2 A[2][4], B[2][4];
                #pragma unroll
                for (int i = 0; i < 4; i++)
                    A[0][i] = *(const ulonglong2*)(aP2 + i * HS);
                #pragma unroll
                for (int j = 0; j < 4; j++)
                    B[0][j] = *(const ulonglong2*)(w2b + j * 16 * W2S);

                #pragma unroll
                for (int q = 0; q < KQ2; ++q) {
                    const int cur = q & 1, nxt = cur ^ 1;
                    if (q + 1 < KQ2) {
                        #pragma unroll
                        for (int i = 0; i < 4; i++)
                            A[nxt][i] = *(const ulonglong2*)(aP2 + i * HS + (q + 1) * 4);
                        #pragma unroll
                        for (int j = 0; j < 4; j++)
                            B[nxt][j] = *(const ulonglong2*)(w2b + j * 16 * W2S + (q + 1) * 4);
                    }
                    #pragma unroll
                    for (int i = 0; i < 4; i++)
                        #pragma unroll
                        for (int j = 0; j < 4; j++) {
                            fma2(zacc[i][j], A[cur][i].x, B[cur][j].x);
                            fma2(zacc[i][j], A[cur][i].y, B[cur][j].y);
                        }
                }
            }
        }

        // ---- epilogue: V and X updates (warp-local) ----
        #pragma unroll
        for (int i = 0; i < 4; i++) {
            float vpart = 0.0f;
            #pragma unroll
            for (int j = 0; j < 4; j++) {
                float2 t = upk(zacc[i][j]);
                float z  = t.x + t.y + b2c[j];
                float wm = sqdt * nz[i][j];
                vpart += z * wm - 0.5f * dt * z * z;
                float* xp = &sX[(r0 + i) * XS + cq + 16 * j];
                float xo = *xp;
                *xp = xo + dt * (thc[j] - xo - z) + wm;
            }
            vpart += __shfl_down_sync(0xffffffffu, vpart, 8, 16);
            vpart += __shfl_down_sync(0xffffffffu, vpart, 4, 16);
            vpart += __shfl_down_sync(0xffffffffu, vpart, 2, 16);
            vpart += __shfl_down_sync(0xffffffffu, vpart, 1, 16);
            vreg[i] += vpart;
        }
        __syncwarp();
    }

    __syncthreads();
    // ---- output: X then V ----
    for (int idx = tid; idx < Rr * Dd; idx += THREADS) {
        int r = idx >> 6, d = idx & 63;
        out[(size_t)(row0 + r) * Dd + d] = sX[r * XS + d];
    }
    if (cq == 0) {
        #pragma unroll
        for (int i = 0; i < 4; i++)
            out[(size_t)Nn * Dd + row0 + r0 + i] = vreg[i];
    }
}

extern "C" void kernel_launch(void* const* d_in, const int* in_sizes, int n_in,
                              void* d_out, int out_size)
{
    (void)in_sizes; (void)n_in; (void)out_size;
    cudaFuncSetAttribute(sim_rollout_kernel,
                         cudaFuncAttributeMaxDynamicSharedMemorySize, SMEM_BYTES);

    transpose_weights<<<64, 256>>>((const float*)d_in[4], (const float*)d_in[6]);
    sim_rollout_kernel<<<NBLOCKS, THREADS, SMEM_BYTES>>>(
        (const float*)d_in[0], (const float*)d_in[1], (const float*)d_in[2],
        (const float*)d_in[3], (const float*)d_in[4], (const float*)d_in[5],
        (const float*)d_in[6], (const float*)d_in[7], (const float*)d_in[8],
        (const int*)d_in[9],   (float*)d_out);
}